// round 14
// baseline (speedup 1.0000x reference)
#include <cuda_runtime.h>
#include <cstdint>

#define Bb   2
#define QLn  256
#define KLn  256
#define QDn  1024
#define Hn   512
#define C3n  1536
#define EPSf 1e-5f

typedef unsigned long long ull;
typedef unsigned int u32;

// ---------------- device scratch (static, no allocation) ----------------
__device__ __align__(16) float g_WqT[QDn*Hn];
__device__ __align__(16) float g_WkT[QDn*Hn];
__device__ __align__(16) float g_AuT[Hn*Hn];     // [j][h] = Wu[h, j]   * lnw[j]
__device__ __align__(16) float g_AvT[Hn*Hn];
__device__ __align__(16) float g_Bu[Hn*Hn];      // [h][j] = Wu[h, H+j] * lnw[H+j]
__device__ __align__(16) float g_Bv[Hn*Hn];
__device__ __align__(16) u32   g_CuF[131072];    // fp16x2 A-fragment pack of Cu' (m16n8k16)
__device__ __align__(16) u32   g_CvF[131072];
__device__ __align__(16) u32   g_kprojH[Bb*KLn*256];  // fp16x2 [b][k][jpair]
__device__ __align__(16) float g_gu[Hn], g_cu[Hn], g_gv[Hn], g_cv[Hn];
__device__ __align__(16) float g_qproj[Bb*QLn*Hn];
__device__ __align__(16) float g_kproj[Bb*KLn*Hn];
__device__ __align__(16) float g_ruq[Bb*QLn*Hn];
__device__ __align__(16) float g_rvq[Bb*QLn*Hn];
__device__ __align__(16) float g_rukT[Bb*Hn*KLn];   // [b][h][k]
__device__ __align__(16) float g_rvkT[Bb*Hn*KLn];
__device__ __align__(16) float g_mu[Bb*QLn*KLn];
__device__ __align__(16) float g_rs[Bb*QLn*KLn];

// ---------------- asm helpers ----------------
__device__ __forceinline__ u32 f16x2(float hi, float lo) {
    u32 d; asm("cvt.rn.f16x2.f32 %0, %1, %2;" : "=r"(d) : "f"(hi), "f"(lo)); return d;
}
__device__ __forceinline__ u32 hmul2(u32 a, u32 b) {
    u32 d; asm("mul.rn.f16x2 %0, %1, %2;" : "=r"(d) : "r"(a), "r"(b)); return d;
}
__device__ __forceinline__ u32 smem_u32(const void* p) {
    u32 a;
    asm("{ .reg .u64 t; cvta.to.shared.u64 t, %1; cvt.u32.u64 %0, t; }" : "=r"(a) : "l"(p));
    return a;
}
__device__ __forceinline__ void cpasync16(u32 s, const void* g) {
    asm volatile("cp.async.cg.shared.global [%0], [%1], 16;" :: "r"(s), "l"(g));
}
__device__ __forceinline__ void cp_commit() { asm volatile("cp.async.commit_group;" ::: "memory"); }
__device__ __forceinline__ void lds128(u32 a, u32* r) {
    asm volatile("ld.shared.v4.b32 {%0,%1,%2,%3}, [%4];"
                 : "=r"(r[0]), "=r"(r[1]), "=r"(r[2]), "=r"(r[3]) : "r"(a));
}
__device__ __forceinline__ u32 lds32(u32 a) {
    u32 r; asm volatile("ld.shared.b32 %0, [%1];" : "=r"(r) : "r"(a)); return r;
}
// D[m=16 h][n=8 k] += A[16x16 fp16] * B[16x8 fp16], fp32 accumulate
__device__ __forceinline__ void mma16(float* d, const u32* a, const u32* b) {
    asm volatile(
        "mma.sync.aligned.m16n8k16.row.col.f32.f16.f16.f32 "
        "{%0,%1,%2,%3}, {%4,%5,%6,%7}, {%8,%9}, {%0,%1,%2,%3};"
        : "+f"(d[0]), "+f"(d[1]), "+f"(d[2]), "+f"(d[3])
        : "r"(a[0]), "r"(a[1]), "r"(a[2]), "r"(a[3]), "r"(b[0]), "r"(b[1]));
}

// ---------------- merged prep kernel (z: 0 WqT, 1 WkT, 2 split, 3 pack, 4 vec) ----
__global__ __launch_bounds__(256) void prep_w(const float* __restrict__ Wq,
                                              const float* __restrict__ Wk,
                                              const float* __restrict__ Wu,
                                              const float* __restrict__ Wv,
                                              const float* __restrict__ lnw,
                                              const float* __restrict__ lnb,
                                              const float* __restrict__ bu,
                                              const float* __restrict__ bv) {
    __shared__ float T[32][33];
    const int t = threadIdx.x, z = blockIdx.z;
    if (z < 2) {
        const float* W = (z == 0) ? Wq : Wk;
        float* WT = (z == 0) ? g_WqT : g_WkT;
        const int x = t & 31, y8 = t >> 5;
        const int th = (blockIdx.x & 15) * 32;   // h tile
        const int td = (blockIdx.x >> 4) * 32;   // d tile
        #pragma unroll
        for (int r = 0; r < 4; r++) {
            int y = y8 + r * 8;
            T[y][x] = W[(size_t)(th + y) * QDn + td + x];
        }
        __syncthreads();
        #pragma unroll
        for (int r = 0; r < 4; r++) {
            int y = y8 + r * 8;
            WT[(size_t)(td + y) * Hn + th + x] = T[x][y];
        }
    } else if (z == 2) {
        for (int i = blockIdx.x * 256 + t; i < Hn * Hn; i += 512 * 256) {
            int h = i & (Hn - 1), j = i >> 9;
            float w0 = lnw[j];
            g_AuT[i] = Wu[(size_t)h * C3n + j] * w0;
            g_AvT[i] = Wv[(size_t)h * C3n + j] * w0;
        }
        for (int i = blockIdx.x * 256 + t; i < Hn * Hn; i += 512 * 256) {
            int j = i & (Hn - 1), h = i >> 9;
            float w1 = lnw[Hn + j];
            g_Bu[i] = Wu[(size_t)h * C3n + Hn + j] * w1;
            g_Bv[i] = Wv[(size_t)h * C3n + Hn + j] * w1;
        }
    } else if (z == 3) {
        // fp16 A-fragment pack (m16n8k16):
        // w = ((((ht*16+jc)*8+mtl)*2+kt)*32+lane)*4 + r
        // h = ht*128+mtl*16+(lane>>2)+8*(r&1), j = jc*32+kt*16+(lane&3)*2+8*(r>>1) (+1 hi)
        for (int w = blockIdx.x * 256 + t; w < 131072; w += 512 * 256) {
            int r = w & 3, lane = (w >> 2) & 31, kt = (w >> 7) & 1, mtl = (w >> 8) & 7;
            int jc = (w >> 11) & 15, ht = (w >> 15) & 3;
            int h = ht * 128 + mtl * 16 + (lane >> 2) + 8 * (r & 1);
            int j = jc * 32 + kt * 16 + (lane & 3) * 2 + 8 * (r >> 1);
            float wl0 = lnw[2 * Hn + j], wl1 = lnw[2 * Hn + j + 1];
            float ul = Wu[(size_t)h * C3n + 2 * Hn + j] * wl0;
            float uh = Wu[(size_t)h * C3n + 2 * Hn + j + 1] * wl1;
            float vl = Wv[(size_t)h * C3n + 2 * Hn + j] * wl0;
            float vh = Wv[(size_t)h * C3n + 2 * Hn + j + 1] * wl1;
            g_CuF[w] = f16x2(uh, ul);
            g_CvF[w] = f16x2(vh, vl);
        }
    } else {
        int gw = blockIdx.x * 8 + (t >> 5);
        int lane = t & 31;
        if (gw >= Hn) return;
        float gu = 0.f, cu = 0.f, gv = 0.f, cv = 0.f;
        for (int c = lane; c < C3n; c += 32) {
            float wl = lnw[c], bl = lnb[c];
            float a = Wu[(size_t)gw * C3n + c], d = Wv[(size_t)gw * C3n + c];
            gu += a * wl; cu += a * bl; gv += d * wl; cv += d * bl;
        }
        #pragma unroll
        for (int o = 16; o; o >>= 1) {
            gu += __shfl_xor_sync(0xffffffffu, gu, o);
            cu += __shfl_xor_sync(0xffffffffu, cu, o);
            gv += __shfl_xor_sync(0xffffffffu, gv, o);
            cv += __shfl_xor_sync(0xffffffffu, cv, o);
        }
        if (lane == 0) {
            g_gu[gw] = gu; g_cu[gw] = cu + bu[gw];
            g_gv[gw] = gv; g_cv[gw] = cv + bv[gw];
        }
    }
}

// ---------------- fp32 GEMM body; NT: C[m][n] = sum_k A[m][k]*B[n][k] ----------------
template<bool NT>
__device__ __forceinline__ void gemm_body(const float* __restrict__ A,
                                          const float* __restrict__ Bm,
                                          float* __restrict__ C,
                                          int N, int Kd, int ldc) {
    __shared__ __align__(16) float As[16][68];
    __shared__ __align__(16) float Bs[16][68];
    const int t  = threadIdx.x;
    const int tx = t & 15, ty = t >> 4;
    const int bm = blockIdx.y * 64, bn = blockIdx.x * 64;
    float acc[4][4] = {};
    for (int kb = 0; kb < Kd; kb += 16) {
        #pragma unroll
        for (int l = 0; l < 4; l++) {
            int e = t + l * 256;
            int m = e >> 4, kk = e & 15;
            As[kk][m] = A[(size_t)(bm + m) * Kd + kb + kk];
            if (NT) {
                Bs[kk][m] = Bm[(size_t)(bn + m) * Kd + kb + kk];
            } else {
                int n = e & 63, k2 = e >> 6;
                Bs[k2][n] = Bm[(size_t)(kb + k2) * N + bn + n];
            }
        }
        __syncthreads();
        #pragma unroll
        for (int kk = 0; kk < 16; kk++) {
            float4 a = *(const float4*)&As[kk][ty * 4];
            float4 b = *(const float4*)&Bs[kk][tx * 4];
            float aw[4] = {a.x, a.y, a.z, a.w};
            float bw[4] = {b.x, b.y, b.z, b.w};
            #pragma unroll
            for (int i = 0; i < 4; i++)
                #pragma unroll
                for (int j = 0; j < 4; j++)
                    acc[i][j] += aw[i] * bw[j];
        }
        __syncthreads();
    }
    #pragma unroll
    for (int i = 0; i < 4; i++) {
        float4 o = make_float4(acc[i][0], acc[i][1], acc[i][2], acc[i][3]);
        *(float4*)&C[(size_t)(bm + ty * 4 + i) * ldc + bn + tx * 4] = o;
    }
}

__global__ __launch_bounds__(256) void gemm_proj(const float* __restrict__ Q,
                                                 const float* __restrict__ K) {
    if (blockIdx.z == 0) gemm_body<false>(Q, g_WqT, g_qproj, Hn, QDn, Hn);
    else                 gemm_body<false>(K, g_WkT, g_kproj, Hn, QDn, Hn);
}

// hidden-term GEMMs + LN stats + fp16 K convert in one launch. grid (8, 64, 8).
__global__ __launch_bounds__(256) void gemm_hs() {
    const int z = blockIdx.z;
    const int t = threadIdx.x;
    if (z < 6) {
        if (blockIdx.y >= 8) return;
        switch (z) {
            case 0: gemm_body<false>(g_qproj, g_AuT, g_ruq, Hn, Hn, Hn); return;
            case 1: gemm_body<false>(g_qproj, g_AvT, g_rvq, Hn, Hn, Hn); return;
            default: break;
        }
        if (blockIdx.x >= 4) return;
        const int b = (z - 2) >> 1;
        const float* kp = g_kproj + (size_t)b * KLn * Hn;
        if ((z & 1) == 0) gemm_body<true>(g_Bu, kp, g_rukT + (size_t)b * Hn * KLn, KLn, Hn, KLn);
        else              gemm_body<true>(g_Bv, kp, g_rvkT + (size_t)b * Hn * KLn, KLn, Hn, KLn);
        return;
    }
    if (z == 7) {
        // fp16x2 convert of kproj
        int i = (blockIdx.y * 8 + blockIdx.x) * 256 + t;   // 0..131071
        g_kprojH[i] = f16x2(g_kproj[2 * i + 1], g_kproj[2 * i]);
        return;
    }
    // z == 6: LN stats; block handles one bq, all 256 k
    __shared__ __align__(16) float qrow[Hn];
    __shared__ float s1s[KLn], s2s[KLn], sqv[2];
    const int warp = t >> 5, lane = t & 31;
    const int bq = blockIdx.y * 8 + blockIdx.x;
    const int b = bq >> 8;
    const float* qp = g_qproj + (size_t)bq * Hn;
    qrow[t] = qp[t]; qrow[t + 256] = qp[t + 256];
    __syncthreads();
    if (warp == 0) {
        float s1 = 0.f, s2 = 0.f;
        #pragma unroll
        for (int j = lane; j < Hn; j += 32) { float v = qrow[j]; s1 += v; s2 += v * v; }
        #pragma unroll
        for (int o = 16; o; o >>= 1) {
            s1 += __shfl_xor_sync(0xffffffffu, s1, o);
            s2 += __shfl_xor_sync(0xffffffffu, s2, o);
        }
        if (lane == 0) { sqv[0] = s1; sqv[1] = s2; }
    }
    const float* kpbase = g_kproj + (size_t)b * KLn * Hn;
    for (int r = 0; r < 32; r++) {
        int kk = warp * 32 + r;
        const float* kp = kpbase + (size_t)kk * Hn;
        float sk = 0.f, sk2 = 0.f, d1 = 0.f, d2 = 0.f;
        for (int j = lane; j < Hn; j += 32) {
            float kv = kp[j];
            float p  = kv * qrow[j];
            sk += kv; sk2 += kv * kv; d1 += p; d2 += p * p;
        }
        #pragma unroll
        for (int o = 16; o; o >>= 1) {
            sk  += __shfl_xor_sync(0xffffffffu, sk,  o);
            sk2 += __shfl_xor_sync(0xffffffffu, sk2, o);
            d1  += __shfl_xor_sync(0xffffffffu, d1,  o);
            d2  += __shfl_xor_sync(0xffffffffu, d2,  o);
        }
        if (lane == 0) { s1s[kk] = sk + d1; s2s[kk] = sk2 + d2; }
    }
    __syncthreads();
    {
        float mu = (sqv[0] + s1s[t]) * (1.f / C3n);
        float e2 = (sqv[1] + s2s[t]) * (1.f / C3n);
        g_mu[(size_t)bq * KLn + t] = mu;
        g_rs[(size_t)bq * KLn + t] = rsqrtf(e2 - mu * mu + EPSf);
    }
}

// ---------------- main mma.sync kernel (fp16 m16n8k16, 2 CTAs/SM, 64-j chunks) ----
// grid (4, 512) = (k-quarter, bq). 256 threads / 8 warps: hg=warp&3 (32h), kg=warp>>2 (32k).
// 64-j chunks (32 iters), depth-2 pipeline with stage AFTER the barrier:
//   iter i: wait_group(0) [stage(i) had a full iter in flight]; barrier;
//           stage(i+1) [writes buffer whose last reads finished before this
//           barrier]; consume buffer i.  One barrier per iter, provably race-free.
#define STAGE_SZ 40960   // CuF 16384 | CvF 16384 | KR 8192 (64 rows x 128B)
#define OFF_STG  0       // 2 stages = 81920
#define OFF_QH   81920   // 1024 (fp16x2 q pairs)
#define OFF_HV   82944   // 4 ht x 7 arrays x 128 floats = 14336
#define OFF_MU   97280   // 256 (holds mu*rs, 64 k)
#define OFF_RS   97536   // 256
#define OFF_SP   97792   // 1024
#define SM_SZ    98816

__global__ __launch_bounds__(256, 2) void gated_mma(const float* __restrict__ Wo,
                                                    const float* __restrict__ bo,
                                                    float* __restrict__ out) {
    extern __shared__ __align__(16) char sm[];
    const u32 sb = smem_u32(sm);
    const int t = threadIdx.x, lane = t & 31, warp = t >> 5;
    const int hg = warp & 3, kg = warp >> 2;        // kg in {0,1}
    const int q = lane >> 2, tid = lane & 3;
    const int kq = blockIdx.x, bq = blockIdx.y, b = bq >> 8;

    // fp16x2 q pairs
    u32* qh = (u32*)(sm + OFF_QH);
    {
        const float* qp = g_qproj + (size_t)bq * Hn + 2 * t;
        qh[t] = f16x2(qp[1], qp[0]);
    }
    float* muS = (float*)(sm + OFF_MU);
    float* rsS = (float*)(sm + OFF_RS);
    if (t < 64) {
        float rs = g_rs[(size_t)bq * KLn + kq * 64 + t];
        rsS[t] = rs;
        muS[t] = g_mu[(size_t)bq * KLn + kq * 64 + t] * rs;   // mu*rs
    }
    // preload epilogue constants for all 4 ht chunks
    float* hvA = (float*)(sm + OFF_HV);
    #pragma unroll
    for (int i = t; i < Hn; i += 256) {
        const int ht = i >> 7, hl = i & 127;
        float* hb = hvA + ht * 896;
        hb[hl]       = g_ruq[(size_t)bq * Hn + i];
        hb[128 + hl] = g_rvq[(size_t)bq * Hn + i];
        hb[256 + hl] = g_gu[i];
        hb[384 + hl] = g_cu[i];
        hb[512 + hl] = g_gv[i];
        hb[640 + hl] = g_cv[i];
        hb[768 + hl] = Wo[i];
    }

    float accU[2][4][4] = {}, accV[2][4][4] = {};
    float part[4][2] = {};

    const char* kpB = (const char*)(g_kprojH + ((size_t)(b * KLn) + kq * 64) * 256);

    // stage s covers j-range [s*64, s*64+64): two jc blocks (2*s, 2*s+1)
    auto stage = [&](int s) {
        const u32 base = sb + OFF_STG + (u32)(s & 1) * STAGE_SZ;
        const char* su = (const char*)(g_CuF + s * 4096);
        const char* sv = (const char*)(g_CvF + s * 4096);
        #pragma unroll
        for (int i = 0; i < 4; i++) {
            int u = t + i * 256;
            cpasync16(base + u * 16,         su + u * 16);
            cpasync16(base + 16384 + u * 16, sv + u * 16);
        }
        // KR: 64 rows x 128B (32 jpairs), chunk-swizzled: (k,c) -> (k>>3)*1024 + c*128 + (k&7)*16
        #pragma unroll
        for (int i = 0; i < 2; i++) {
            int ch = t + i * 256;
            int k = ch >> 3, c = ch & 7;
            u32 dst = base + 32768 + (u32)((k >> 3) * 1024 + c * 128 + (k & 7) * 16);
            cpasync16(dst, kpB + (size_t)k * 1024 + (s & 7) * 128 + c * 16);
        }
        cp_commit();
    };

    stage(0);

    // per-lane constant base into swizzled KR (block kb = ntc = kg*4+nt, row q, word tid)
    const u32 krOff = (u32)(kg * 4 * 1024 + q * 16 + tid * 4);

    for (int it = 0; it < 32; it++) {
        asm volatile("cp.async.wait_group 0;" ::: "memory");
        __syncthreads();
        if (it < 31) stage(it + 1);   // safe: writes buffer whose reads ended before this barrier

        const u32 base = sb + OFF_STG + (u32)(it & 1) * STAGE_SZ;
        const u32 aU = base, aV = base + 16384;
        const u32 krb = base + 32768 + krOff;
        const u32 qhb = sb + OFF_QH + (u32)(((it & 7) * 64 + tid * 2) * 2);

        #pragma unroll
        for (int kt = 0; kt < 4; kt++) {
            const u32 qh0 = lds32(qhb + (u32)(kt * 32));
            const u32 qh1 = lds32(qhb + (u32)(kt * 32 + 16));
            u32 bfr[4][2];
            #pragma unroll
            for (int nt = 0; nt < 4; nt++) {
                const u32 a0 = krb + (u32)(nt * 1024 + kt * 256);
                u32 k0 = lds32(a0);
                u32 k1 = lds32(a0 + 128);
                bfr[nt][0] = hmul2(k0, qh0);
                bfr[nt][1] = hmul2(k1, qh1);
            }
            u32 au[2][4], av[2][4];
            #pragma unroll
            for (int mt = 0; mt < 2; mt++) {
                const u32 fo = (u32)((kt >> 1) * 8192) +
                               (u32)((((hg * 2 + mt) * 2 + (kt & 1)) * 32 + lane) * 16);
                lds128(aU + fo, au[mt]);
                lds128(aV + fo, av[mt]);
            }
            #pragma unroll
            for (int mt = 0; mt < 2; mt++)
                #pragma unroll
                for (int nt = 0; nt < 4; nt++) {
                    mma16(accU[mt][nt], au[mt], bfr[nt]);
                    mma16(accV[mt][nt], av[mt], bfr[nt]);
                }
        }

        if ((it & 7) == 7) {
            const int ht = it >> 3;
            const float* hv = hvA + ht * 896;
            const float* ruT = g_rukT + ((size_t)b * Hn + ht * 128) * KLn + kq * 64;
            const float* rvT = g_rvkT + ((size_t)b * Hn + ht * 128) * KLn + kq * 64;
            #pragma unroll
            for (int mt = 0; mt < 2; mt++) {
                #pragma unroll
                for (int rr = 0; rr < 2; rr++) {
                    const int hl = (hg * 2 + mt) * 16 + q + rr * 8;
                    const float ruq = hv[hl],       rvq = hv[128 + hl];
                    const float gu  = hv[256 + hl], cu  = hv[384 + hl];
                    const float gv  = hv[512 + hl], cv  = hv[640 + hl];
                    const float wo  = hv[768 + hl];
                    const float* ruB = ruT + (size_t)hl * KLn + kg * 32 + tid * 2;
                    const float* rvB = rvT + (size_t)hl * KLn + kg * 32 + tid * 2;
                    #pragma unroll
                    for (int nt = 0; nt < 4; nt++) {
                        float2 ru2 = *(const float2*)(ruB + nt * 8);
                        float2 rv2 = *(const float2*)(rvB + nt * 8);
                        #pragma unroll
                        for (int e = 0; e < 2; e++) {
                            const int kc = kg * 32 + nt * 8 + tid * 2 + e;
                            const float mrs = muS[kc], rs = rsS[kc];
                            const float du = accU[mt][nt][rr * 2 + e];
                            const float dv = accV[mt][nt][rr * 2 + e];
                            const float ruk = e ? ru2.y : ru2.x;
                            const float rvk = e ? rv2.y : rv2.x;
                            float U = rs * (du + ruq + ruk) - mrs * gu + cu;
                            float V = rs * (dv + rvq + rvk) - mrs * gv + cv;
                            float G = 0.5f * V * (1.0f + erff(V * 0.70710678118654752440f));
                            part[nt][e] += wo * (U * G);
                            accU[mt][nt][rr * 2 + e] = 0.f;
                            accV[mt][nt][rr * 2 + e] = 0.f;
                        }
                    }
                }
            }
        }
    }

    // reduce across q-lanes (same tid), then across the 4 hg warps via smem
    #pragma unroll
    for (int nt = 0; nt < 4; nt++)
        #pragma unroll
        for (int e = 0; e < 2; e++) {
            float v = part[nt][e];
            v += __shfl_xor_sync(0xffffffffu, v, 4);
            v += __shfl_xor_sync(0xffffffffu, v, 8);
            v += __shfl_xor_sync(0xffffffffu, v, 16);
            part[nt][e] = v;
        }
    float* sp = (float*)(sm + OFF_SP);
    __syncthreads();
    if (q == 0) {
        #pragma unroll
        for (int nt = 0; nt < 4; nt++)
            #pragma unroll
            for (int e = 0; e < 2; e++)
                sp[hg * 64 + kg * 32 + nt * 8 + tid * 2 + e] = part[nt][e];
    }
    __syncthreads();
    if (t < 64) {
        float r = sp[t] + sp[64 + t] + sp[128 + t] + sp[192 + t] + bo[0];
        out[(size_t)bq * KLn + kq * 64 + t] = r;
    }
}

// ---------------- launch ----------------
extern "C" void kernel_launch(void* const* d_in, const int* in_sizes, int n_in,
                              void* d_out, int out_size) {
    const float* Q   = (const float*)d_in[0];
    const float* K   = (const float*)d_in[1];
    const float* Wq  = (const float*)d_in[2];
    const float* Wk  = (const float*)d_in[3];
    const float* lnw = (const float*)d_in[4];
    const float* lnb = (const float*)d_in[5];
    const float* Wu  = (const float*)d_in[6];
    const float* bu  = (const float*)d_in[7];
    const float* Wv  = (const float*)d_in[8];
    const float* bv  = (const float*)d_in[9];
    const float* Wo  = (const float*)d_in[10];
    const float* bo  = (const float*)d_in[11];
    float* out = (float*)d_out;

    static int smem_set = 0;
    if (!smem_set) {
        cudaFuncSetAttribute(gated_mma, cudaFuncAttributeMaxDynamicSharedMemorySize, SM_SZ);
        smem_set = 1;
    }

    prep_w<<<dim3(512, 1, 5), 256>>>(Wq, Wk, Wu, Wv, lnw, lnb, bu, bv);
    gemm_proj<<<dim3(8, 8, 2), 256>>>(Q, K);
    gemm_hs<<<dim3(8, 64, 8), 256>>>();
    gated_mma<<<dim3(4, 512), 256, SM_SZ>>>(Wo, bo, out);
}

// round 15
// speedup vs baseline: 1.0260x; 1.0260x over previous
#include <cuda_runtime.h>
#include <cstdint>

#define Bb   2
#define QLn  256
#define KLn  256
#define QDn  1024
#define Hn   512
#define C3n  1536
#define EPSf 1e-5f

typedef unsigned long long ull;
typedef unsigned int u32;

// ---------------- device scratch (static, no allocation) ----------------
__device__ __align__(16) float g_AuT[Hn*Hn];     // [j][h] = Wu[h, j]   * lnw[j]
__device__ __align__(16) float g_AvT[Hn*Hn];
__device__ __align__(16) float g_Bu[Hn*Hn];      // [h][j] = Wu[h, H+j] * lnw[H+j]
__device__ __align__(16) float g_Bv[Hn*Hn];
__device__ __align__(16) u32   g_CuF[131072];    // fp16x2 A-fragment pack of Cu' (m16n8k16)
__device__ __align__(16) u32   g_CvF[131072];
__device__ __align__(16) u32   g_kprojH[Bb*KLn*256];  // fp16x2 [b][k][jpair]
__device__ __align__(16) float g_gu[Hn], g_cu[Hn], g_gv[Hn], g_cv[Hn];
__device__ __align__(16) float g_qproj[Bb*QLn*Hn];
__device__ __align__(16) float g_kproj[Bb*KLn*Hn];
__device__ __align__(16) float g_ruq[Bb*QLn*Hn];
__device__ __align__(16) float g_rvq[Bb*QLn*Hn];
__device__ __align__(16) float g_rukT[Bb*Hn*KLn];   // [b][h][k]
__device__ __align__(16) float g_rvkT[Bb*Hn*KLn];
__device__ __align__(16) float g_mu[Bb*QLn*KLn];
__device__ __align__(16) float g_rs[Bb*QLn*KLn];

// ---------------- asm helpers ----------------
__device__ __forceinline__ u32 f16x2(float hi, float lo) {
    u32 d; asm("cvt.rn.f16x2.f32 %0, %1, %2;" : "=r"(d) : "f"(hi), "f"(lo)); return d;
}
__device__ __forceinline__ u32 hmul2(u32 a, u32 b) {
    u32 d; asm("mul.rn.f16x2 %0, %1, %2;" : "=r"(d) : "r"(a), "r"(b)); return d;
}
__device__ __forceinline__ u32 smem_u32(const void* p) {
    u32 a;
    asm("{ .reg .u64 t; cvta.to.shared.u64 t, %1; cvt.u32.u64 %0, t; }" : "=r"(a) : "l"(p));
    return a;
}
__device__ __forceinline__ void cpasync16(u32 s, const void* g) {
    asm volatile("cp.async.cg.shared.global [%0], [%1], 16;" :: "r"(s), "l"(g));
}
__device__ __forceinline__ void cp_commit() { asm volatile("cp.async.commit_group;" ::: "memory"); }
__device__ __forceinline__ void lds128(u32 a, u32* r) {
    asm volatile("ld.shared.v4.b32 {%0,%1,%2,%3}, [%4];"
                 : "=r"(r[0]), "=r"(r[1]), "=r"(r[2]), "=r"(r[3]) : "r"(a));
}
__device__ __forceinline__ u32 lds32(u32 a) {
    u32 r; asm volatile("ld.shared.b32 %0, [%1];" : "=r"(r) : "r"(a)); return r;
}
// D[m=16 h][n=8 k] += A[16x16 fp16] * B[16x8 fp16], fp32 accumulate
__device__ __forceinline__ void mma16(float* d, const u32* a, const u32* b) {
    asm volatile(
        "mma.sync.aligned.m16n8k16.row.col.f32.f16.f16.f32 "
        "{%0,%1,%2,%3}, {%4,%5,%6,%7}, {%8,%9}, {%0,%1,%2,%3};"
        : "+f"(d[0]), "+f"(d[1]), "+f"(d[2]), "+f"(d[3])
        : "r"(a[0]), "r"(a[1]), "r"(a[2]), "r"(a[3]), "r"(b[0]), "r"(b[1]));
}

// ---------------- merged prep kernel (z: 0 split, 1 pack, 2 vec) ----
__global__ __launch_bounds__(256) void prep_w(const float* __restrict__ Wu,
                                              const float* __restrict__ Wv,
                                              const float* __restrict__ lnw,
                                              const float* __restrict__ lnb,
                                              const float* __restrict__ bu,
                                              const float* __restrict__ bv) {
    const int t = threadIdx.x, z = blockIdx.z;
    if (z == 0) {
        for (int i = blockIdx.x * 256 + t; i < Hn * Hn; i += 512 * 256) {
            int h = i & (Hn - 1), j = i >> 9;
            float w0 = lnw[j];
            g_AuT[i] = Wu[(size_t)h * C3n + j] * w0;
            g_AvT[i] = Wv[(size_t)h * C3n + j] * w0;
        }
        for (int i = blockIdx.x * 256 + t; i < Hn * Hn; i += 512 * 256) {
            int j = i & (Hn - 1), h = i >> 9;
            float w1 = lnw[Hn + j];
            g_Bu[i] = Wu[(size_t)h * C3n + Hn + j] * w1;
            g_Bv[i] = Wv[(size_t)h * C3n + Hn + j] * w1;
        }
    } else if (z == 1) {
        // fp16 A-fragment pack (m16n8k16):
        // w = ((((ht*16+jc)*8+mtl)*2+kt)*32+lane)*4 + r
        // h = ht*128+mtl*16+(lane>>2)+8*(r&1), j = jc*32+kt*16+(lane&3)*2+8*(r>>1) (+1 hi)
        for (int w = blockIdx.x * 256 + t; w < 131072; w += 512 * 256) {
            int r = w & 3, lane = (w >> 2) & 31, kt = (w >> 7) & 1, mtl = (w >> 8) & 7;
            int jc = (w >> 11) & 15, ht = (w >> 15) & 3;
            int h = ht * 128 + mtl * 16 + (lane >> 2) + 8 * (r & 1);
            int j = jc * 32 + kt * 16 + (lane & 3) * 2 + 8 * (r >> 1);
            float wl0 = lnw[2 * Hn + j], wl1 = lnw[2 * Hn + j + 1];
            float ul = Wu[(size_t)h * C3n + 2 * Hn + j] * wl0;
            float uh = Wu[(size_t)h * C3n + 2 * Hn + j + 1] * wl1;
            float vl = Wv[(size_t)h * C3n + 2 * Hn + j] * wl0;
            float vh = Wv[(size_t)h * C3n + 2 * Hn + j + 1] * wl1;
            g_CuF[w] = f16x2(uh, ul);
            g_CvF[w] = f16x2(vh, vl);
        }
    } else {
        int gw = blockIdx.x * 8 + (t >> 5);
        int lane = t & 31;
        if (gw >= Hn) return;
        float gu = 0.f, cu = 0.f, gv = 0.f, cv = 0.f;
        for (int c = lane; c < C3n; c += 32) {
            float wl = lnw[c], bl = lnb[c];
            float a = Wu[(size_t)gw * C3n + c], d = Wv[(size_t)gw * C3n + c];
            gu += a * wl; cu += a * bl; gv += d * wl; cv += d * bl;
        }
        #pragma unroll
        for (int o = 16; o; o >>= 1) {
            gu += __shfl_xor_sync(0xffffffffu, gu, o);
            cu += __shfl_xor_sync(0xffffffffu, cu, o);
            gv += __shfl_xor_sync(0xffffffffu, gv, o);
            cv += __shfl_xor_sync(0xffffffffu, cv, o);
        }
        if (lane == 0) {
            g_gu[gw] = gu; g_cu[gw] = cu + bu[gw];
            g_gv[gw] = gv; g_cv[gw] = cv + bv[gw];
        }
    }
}

// ---------------- fp32 GEMM body; NT: C[m][n] = sum_k A[m][k]*B[n][k] ----------------
template<bool NT>
__device__ __forceinline__ void gemm_body(const float* __restrict__ A,
                                          const float* __restrict__ Bm,
                                          float* __restrict__ C,
                                          int N, int Kd, int ldc) {
    __shared__ __align__(16) float As[16][68];
    __shared__ __align__(16) float Bs[16][68];
    const int t  = threadIdx.x;
    const int tx = t & 15, ty = t >> 4;
    const int bm = blockIdx.y * 64, bn = blockIdx.x * 64;
    float acc[4][4] = {};
    for (int kb = 0; kb < Kd; kb += 16) {
        #pragma unroll
        for (int l = 0; l < 4; l++) {
            int e = t + l * 256;
            int m = e >> 4, kk = e & 15;
            As[kk][m] = A[(size_t)(bm + m) * Kd + kb + kk];
            if (NT) {
                Bs[kk][m] = Bm[(size_t)(bn + m) * Kd + kb + kk];
            } else {
                int n = e & 63, k2 = e >> 6;
                Bs[k2][n] = Bm[(size_t)(kb + k2) * N + bn + n];
            }
        }
        __syncthreads();
        #pragma unroll
        for (int kk = 0; kk < 16; kk++) {
            float4 a = *(const float4*)&As[kk][ty * 4];
            float4 b = *(const float4*)&Bs[kk][tx * 4];
            float aw[4] = {a.x, a.y, a.z, a.w};
            float bw[4] = {b.x, b.y, b.z, b.w};
            #pragma unroll
            for (int i = 0; i < 4; i++)
                #pragma unroll
                for (int j = 0; j < 4; j++)
                    acc[i][j] += aw[i] * bw[j];
        }
        __syncthreads();
    }
    #pragma unroll
    for (int i = 0; i < 4; i++) {
        float4 o = make_float4(acc[i][0], acc[i][1], acc[i][2], acc[i][3]);
        *(float4*)&C[(size_t)(bm + ty * 4 + i) * ldc + bn + tx * 4] = o;
    }
}

// NT projections directly on raw weights: qproj[m][h] = sum_d Q[m][d]*Wq[h][d]
__global__ __launch_bounds__(256) void gemm_proj(const float* __restrict__ Q,
                                                 const float* __restrict__ K,
                                                 const float* __restrict__ Wq,
                                                 const float* __restrict__ Wk) {
    if (blockIdx.z == 0) gemm_body<true>(Q, Wq, g_qproj, Hn, QDn, Hn);
    else                 gemm_body<true>(K, Wk, g_kproj, Hn, QDn, Hn);
}

// hidden-term GEMMs + LN stats + fp16 K convert in one launch. grid (8, 64, 8).
__global__ __launch_bounds__(256) void gemm_hs() {
    const int z = blockIdx.z;
    const int t = threadIdx.x;
    if (z < 6) {
        if (blockIdx.y >= 8) return;
        switch (z) {
            case 0: gemm_body<false>(g_qproj, g_AuT, g_ruq, Hn, Hn, Hn); return;
            case 1: gemm_body<false>(g_qproj, g_AvT, g_rvq, Hn, Hn, Hn); return;
            default: break;
        }
        if (blockIdx.x >= 4) return;
        const int b = (z - 2) >> 1;
        const float* kp = g_kproj + (size_t)b * KLn * Hn;
        if ((z & 1) == 0) gemm_body<true>(g_Bu, kp, g_rukT + (size_t)b * Hn * KLn, KLn, Hn, KLn);
        else              gemm_body<true>(g_Bv, kp, g_rvkT + (size_t)b * Hn * KLn, KLn, Hn, KLn);
        return;
    }
    if (z == 7) {
        // fp16x2 convert of kproj
        int i = (blockIdx.y * 8 + blockIdx.x) * 256 + t;   // 0..131071
        g_kprojH[i] = f16x2(g_kproj[2 * i + 1], g_kproj[2 * i]);
        return;
    }
    // z == 6: LN stats; block handles one bq, all 256 k
    __shared__ __align__(16) float qrow[Hn];
    __shared__ float s1s[KLn], s2s[KLn], sqv[2];
    const int warp = t >> 5, lane = t & 31;
    const int bq = blockIdx.y * 8 + blockIdx.x;
    const int b = bq >> 8;
    const float* qp = g_qproj + (size_t)bq * Hn;
    qrow[t] = qp[t]; qrow[t + 256] = qp[t + 256];
    __syncthreads();
    if (warp == 0) {
        float s1 = 0.f, s2 = 0.f;
        #pragma unroll
        for (int j = lane; j < Hn; j += 32) { float v = qrow[j]; s1 += v; s2 += v * v; }
        #pragma unroll
        for (int o = 16; o; o >>= 1) {
            s1 += __shfl_xor_sync(0xffffffffu, s1, o);
            s2 += __shfl_xor_sync(0xffffffffu, s2, o);
        }
        if (lane == 0) { sqv[0] = s1; sqv[1] = s2; }
    }
    const float* kpbase = g_kproj + (size_t)b * KLn * Hn;
    for (int r = 0; r < 32; r++) {
        int kk = warp * 32 + r;
        const float* kp = kpbase + (size_t)kk * Hn;
        float sk = 0.f, sk2 = 0.f, d1 = 0.f, d2 = 0.f;
        for (int j = lane; j < Hn; j += 32) {
            float kv = kp[j];
            float p  = kv * qrow[j];
            sk += kv; sk2 += kv * kv; d1 += p; d2 += p * p;
        }
        #pragma unroll
        for (int o = 16; o; o >>= 1) {
            sk  += __shfl_xor_sync(0xffffffffu, sk,  o);
            sk2 += __shfl_xor_sync(0xffffffffu, sk2, o);
            d1  += __shfl_xor_sync(0xffffffffu, d1,  o);
            d2  += __shfl_xor_sync(0xffffffffu, d2,  o);
        }
        if (lane == 0) { s1s[kk] = sk + d1; s2s[kk] = sk2 + d2; }
    }
    __syncthreads();
    {
        float mu = (sqv[0] + s1s[t]) * (1.f / C3n);
        float e2 = (sqv[1] + s2s[t]) * (1.f / C3n);
        g_mu[(size_t)bq * KLn + t] = mu;
        g_rs[(size_t)bq * KLn + t] = rsqrtf(e2 - mu * mu + EPSf);
    }
}

// ---------------- main mma.sync kernel (fp16 m16n8k16, 2 CTAs/SM) ----------------
// grid (4, 512) = (k-quarter, bq). 256 threads / 8 warps: hg=warp&3 (32h), kg=warp>>2 (32k).
// 32-j chunks, DEPTH-3 pipeline, stage AFTER barrier with d=2 lead:
//   iter i: wait_group(1) [stage(i) done, stage(i+1) may fly]; barrier;
//           stage(i+2) [writes chunk i-1's buffer; its reads ended before barrier];
//           consume chunk i.  One barrier/iter, two iterations of staging lead.
#define STAGE_SZ 20480   // CuF 8192 | CvF 8192 | KR 4096 (64 rows)
#define OFF_STG  0       // 3 stages = 61440
#define OFF_QH   61440   // 1024 (fp16x2 q pairs)
#define OFF_HV   62464   // 4 ht x 7 arrays x 128 floats = 14336
#define OFF_MU   76800   // 256 (holds mu*rs, 64 k)
#define OFF_RS   77056   // 256
#define OFF_SP   77312   // 1024
#define SM_SZ    78336

__global__ __launch_bounds__(256, 2) void gated_mma(const float* __restrict__ Wo,
                                                    const float* __restrict__ bo,
                                                    float* __restrict__ out) {
    extern __shared__ __align__(16) char sm[];
    const u32 sb = smem_u32(sm);
    const int t = threadIdx.x, lane = t & 31, warp = t >> 5;
    const int hg = warp & 3, kg = warp >> 2;        // kg in {0,1}
    const int q = lane >> 2, tid = lane & 3;
    const int kq = blockIdx.x, bq = blockIdx.y, b = bq >> 8;

    // fp16x2 q pairs
    u32* qh = (u32*)(sm + OFF_QH);
    {
        const float* qp = g_qproj + (size_t)bq * Hn + 2 * t;
        qh[t] = f16x2(qp[1], qp[0]);
    }
    float* muS = (float*)(sm + OFF_MU);
    float* rsS = (float*)(sm + OFF_RS);
    if (t < 64) {
        float rs = g_rs[(size_t)bq * KLn + kq * 64 + t];
        rsS[t] = rs;
        muS[t] = g_mu[(size_t)bq * KLn + kq * 64 + t] * rs;   // mu*rs
    }
    // preload epilogue constants for all 4 ht chunks
    float* hvA = (float*)(sm + OFF_HV);
    #pragma unroll
    for (int i = t; i < Hn; i += 256) {
        const int ht = i >> 7, hl = i & 127;
        float* hb = hvA + ht * 896;
        hb[hl]       = g_ruq[(size_t)bq * Hn + i];
        hb[128 + hl] = g_rvq[(size_t)bq * Hn + i];
        hb[256 + hl] = g_gu[i];
        hb[384 + hl] = g_cu[i];
        hb[512 + hl] = g_gv[i];
        hb[640 + hl] = g_cv[i];
        hb[768 + hl] = Wo[i];
    }

    float accU[2][4][4] = {}, accV[2][4][4] = {};
    float part[4][2] = {};

    const char* kpB = (const char*)(g_kprojH + ((size_t)(b * KLn) + kq * 64) * 256);

    auto stage = [&](int s) {
        const int jc = s & 15;
        const u32 base = sb + OFF_STG + (u32)(s % 3) * STAGE_SZ;
        const char* su = (const char*)(g_CuF + s * 2048);
        const char* sv = (const char*)(g_CvF + s * 2048);
        cpasync16(base + t * 16,               su + t * 16);
        cpasync16(base + (t + 256) * 16,       su + (t + 256) * 16);
        cpasync16(base + 8192 + t * 16,        sv + t * 16);
        cpasync16(base + 8192 + (t + 256) * 16, sv + (t + 256) * 16);
        // KR: 256 chunks of 16B (64 rows), chunk-swizzled
        {
            int k = t >> 2, c = t & 3;
            u32 dst = base + 16384 + (u32)((k >> 3) * 512 + c * 128 + (k & 7) * 16);
            cpasync16(dst, kpB + (size_t)k * 1024 + jc * 64 + c * 16);
        }
        cp_commit();
    };

    stage(0); stage(1);

    // per-lane constant base into swizzled KR (block = kg*4 + nt, row q', word tid)
    const u32 krOff = (u32)(kg * 4 * 512 + q * 16 + tid * 4);

    for (int it = 0; it < 64; it++) {
        if (it < 63) asm volatile("cp.async.wait_group 1;" ::: "memory");
        else         asm volatile("cp.async.wait_group 0;" ::: "memory");
        __syncthreads();
        if (it < 62) stage(it + 2);   // writes chunk it-1's buffer; reads done pre-barrier

        const u32 base = sb + OFF_STG + (u32)(it % 3) * STAGE_SZ;
        const u32 aU = base, aV = base + 8192;
        const u32 krb = base + 16384 + krOff;
        const u32 qhb = sb + OFF_QH + (u32)(((it & 15) * 16 + tid) * 4);

        #pragma unroll
        for (int kt = 0; kt < 2; kt++) {
            const u32 qh0 = lds32(qhb + (u32)(kt * 32));
            const u32 qh1 = lds32(qhb + (u32)(kt * 32 + 16));
            u32 bfr[4][2];
            #pragma unroll
            for (int nt = 0; nt < 4; nt++) {
                const u32 a0 = krb + (u32)(nt * 512 + kt * 256);
                u32 k0 = lds32(a0);
                u32 k1 = lds32(a0 + 128);
                bfr[nt][0] = hmul2(k0, qh0);
                bfr[nt][1] = hmul2(k1, qh1);
            }
            u32 au[2][4], av[2][4];
            #pragma unroll
            for (int mt = 0; mt < 2; mt++) {
                const u32 fo = (u32)((((hg * 2 + mt) * 2 + kt) * 32 + lane) * 16);
                lds128(aU + fo, au[mt]);
                lds128(aV + fo, av[mt]);
            }
            #pragma unroll
            for (int mt = 0; mt < 2; mt++)
                #pragma unroll
                for (int nt = 0; nt < 4; nt++) {
                    mma16(accU[mt][nt], au[mt], bfr[nt]);
                    mma16(accV[mt][nt], av[mt], bfr[nt]);
                }
        }

        if ((it & 15) == 15) {
            const int ht = it >> 4;
            const float* hv = hvA + ht * 896;
            const float* ruT = g_rukT + ((size_t)b * Hn + ht * 128) * KLn + kq * 64;
            const float* rvT = g_rvkT + ((size_t)b * Hn + ht * 128) * KLn + kq * 64;
            #pragma unroll
            for (int mt = 0; mt < 2; mt++) {
                #pragma unroll
                for (int rr = 0; rr < 2; rr++) {
                    const int hl = (hg * 2 + mt) * 16 + q + rr * 8;
                    const float ruq = hv[hl],       rvq = hv[128 + hl];
                    const float gu  = hv[256 + hl], cu  = hv[384 + hl];
                    const float gv  = hv[512 + hl], cv  = hv[640 + hl];
                    const float wo  = hv[768 + hl];
                    const float* ruB = ruT + (size_t)hl * KLn + kg * 32 + tid * 2;
                    const float* rvB = rvT + (size_t)hl * KLn + kg * 32 + tid * 2;
                    #pragma unroll
                    for (int nt = 0; nt < 4; nt++) {
                        float2 ru2 = *(const float2*)(ruB + nt * 8);
                        float2 rv2 = *(const float2*)(rvB + nt * 8);
                        #pragma unroll
                        for (int e = 0; e < 2; e++) {
                            const int kc = kg * 32 + nt * 8 + tid * 2 + e;
                            const float mrs = muS[kc], rs = rsS[kc];
                            const float du = accU[mt][nt][rr * 2 + e];
                            const float dv = accV[mt][nt][rr * 2 + e];
                            const float ruk = e ? ru2.y : ru2.x;
                            const float rvk = e ? rv2.y : rv2.x;
                            float U = rs * (du + ruq + ruk) - mrs * gu + cu;
                            float V = rs * (dv + rvq + rvk) - mrs * gv + cv;
                            float G = 0.5f * V * (1.0f + erff(V * 0.70710678118654752440f));
                            part[nt][e] += wo * (U * G);
                            accU[mt][nt][rr * 2 + e] = 0.f;
                            accV[mt][nt][rr * 2 + e] = 0.f;
                        }
                    }
                }
            }
        }
    }

    // reduce across q-lanes (same tid), then across the 4 hg warps via smem
    #pragma unroll
    for (int nt = 0; nt < 4; nt++)
        #pragma unroll
        for (int e = 0; e < 2; e++) {
            float v = part[nt][e];
            v += __shfl_xor_sync(0xffffffffu, v, 4);
            v += __shfl_xor_sync(0xffffffffu, v, 8);
            v += __shfl_xor_sync(0xffffffffu, v, 16);
            part[nt][e] = v;
        }
    float* sp = (float*)(sm + OFF_SP);
    __syncthreads();
    if (q == 0) {
        #pragma unroll
        for (int nt = 0; nt < 4; nt++)
            #pragma unroll
            for (int e = 0; e < 2; e++)
                sp[hg * 64 + kg * 32 + nt * 8 + tid * 2 + e] = part[nt][e];
    }
    __syncthreads();
    if (t < 64) {
        float r = sp[t] + sp[64 + t] + sp[128 + t] + sp[192 + t] + bo[0];
        out[(size_t)bq * KLn + kq * 64 + t] = r;
    }
}

// ---------------- launch ----------------
extern "C" void kernel_launch(void* const* d_in, const int* in_sizes, int n_in,
                              void* d_out, int out_size) {
    const float* Q   = (const float*)d_in[0];
    const float* K   = (const float*)d_in[1];
    const float* Wq  = (const float*)d_in[2];
    const float* Wk  = (const float*)d_in[3];
    const float* lnw = (const float*)d_in[4];
    const float* lnb = (const float*)d_in[5];
    const float* Wu  = (const float*)d_in[6];
    const float* bu  = (const float*)d_in[7];
    const float* Wv  = (const float*)d_in[8];
    const float* bv  = (const float*)d_in[9];
    const float* Wo  = (const float*)d_in[10];
    const float* bo  = (const float*)d_in[11];
    float* out = (float*)d_out;

    static int smem_set = 0;
    if (!smem_set) {
        cudaFuncSetAttribute(gated_mma, cudaFuncAttributeMaxDynamicSharedMemorySize, SM_SZ);
        smem_set = 1;
    }

    prep_w<<<dim3(512, 1, 3), 256>>>(Wu, Wv, lnw, lnb, bu, bv);
    gemm_proj<<<dim3(8, 8, 2), 256>>>(Q, K, Wq, Wk);
    gemm_hs<<<dim3(8, 64, 8), 256>>>();
    gated_mma<<<dim3(4, 512), 256, SM_SZ>>>(Wo, bo, out);
}

// round 16
// speedup vs baseline: 1.1097x; 1.0816x over previous
#include <cuda_runtime.h>
#include <cstdint>

#define Bb   2
#define QLn  256
#define KLn  256
#define QDn  1024
#define Hn   512
#define C3n  1536
#define EPSf 1e-5f

typedef unsigned long long ull;
typedef unsigned int u32;

// ---------------- device scratch (static, no allocation) ----------------
__device__ __align__(16) float g_AuT[Hn*Hn];     // [j][h] = Wu[h, j]   * lnw[j]
__device__ __align__(16) float g_AvT[Hn*Hn];
__device__ __align__(16) float g_Bu[Hn*Hn];      // [h][j] = Wu[h, H+j] * lnw[H+j]
__device__ __align__(16) float g_Bv[Hn*Hn];
__device__ __align__(16) u32   g_CuF[131072];    // fp16x2 A-fragment pack of Cu' (m16n8k16)
__device__ __align__(16) u32   g_CvF[131072];
__device__ __align__(16) u32   g_kprojH[Bb*KLn*256];  // fp16x2 [b][k][jpair]
__device__ __align__(16) float g_gu[Hn], g_cu[Hn], g_gv[Hn], g_cv[Hn];
__device__ __align__(16) float g_qproj[Bb*QLn*Hn];
__device__ __align__(16) float g_kproj[Bb*KLn*Hn];
__device__ __align__(16) float g_ruq[Bb*QLn*Hn];
__device__ __align__(16) float g_rvq[Bb*QLn*Hn];
__device__ __align__(16) float g_rukT[Bb*Hn*KLn];   // [b][h][k]
__device__ __align__(16) float g_rvkT[Bb*Hn*KLn];
__device__ __align__(16) float g_mu[Bb*QLn*KLn];
__device__ __align__(16) float g_rs[Bb*QLn*KLn];

// ---------------- asm helpers ----------------
__device__ __forceinline__ u32 f16x2(float hi, float lo) {
    u32 d; asm("cvt.rn.f16x2.f32 %0, %1, %2;" : "=r"(d) : "f"(hi), "f"(lo)); return d;
}
__device__ __forceinline__ u32 hmul2(u32 a, u32 b) {
    u32 d; asm("mul.rn.f16x2 %0, %1, %2;" : "=r"(d) : "r"(a), "r"(b)); return d;
}
__device__ __forceinline__ u32 smem_u32(const void* p) {
    u32 a;
    asm("{ .reg .u64 t; cvta.to.shared.u64 t, %1; cvt.u32.u64 %0, t; }" : "=r"(a) : "l"(p));
    return a;
}
__device__ __forceinline__ void cpasync16(u32 s, const void* g) {
    asm volatile("cp.async.cg.shared.global [%0], [%1], 16;" :: "r"(s), "l"(g));
}
__device__ __forceinline__ void cp_commit() { asm volatile("cp.async.commit_group;" ::: "memory"); }
__device__ __forceinline__ void lds128(u32 a, u32* r) {
    asm volatile("ld.shared.v4.b32 {%0,%1,%2,%3}, [%4];"
                 : "=r"(r[0]), "=r"(r[1]), "=r"(r[2]), "=r"(r[3]) : "r"(a));
}
__device__ __forceinline__ u32 lds32(u32 a) {
    u32 r; asm volatile("ld.shared.b32 %0, [%1];" : "=r"(r) : "r"(a)); return r;
}
// D[m=16 h][n=8 k] += A[16x16 fp16] * B[16x8 fp16], fp32 accumulate
__device__ __forceinline__ void mma16(float* d, const u32* a, const u32* b) {
    asm volatile(
        "mma.sync.aligned.m16n8k16.row.col.f32.f16.f16.f32 "
        "{%0,%1,%2,%3}, {%4,%5,%6,%7}, {%8,%9}, {%0,%1,%2,%3};"
        : "+f"(d[0]), "+f"(d[1]), "+f"(d[2]), "+f"(d[3])
        : "r"(a[0]), "r"(a[1]), "r"(a[2]), "r"(a[3]), "r"(b[0]), "r"(b[1]));
}

// ---------------- merged prep kernel (z: 0 split, 1 pack, 2 vec) ----
__global__ __launch_bounds__(256) void prep_w(const float* __restrict__ Wu,
                                              const float* __restrict__ Wv,
                                              const float* __restrict__ lnw,
                                              const float* __restrict__ lnb,
                                              const float* __restrict__ bu,
                                              const float* __restrict__ bv) {
    const int t = threadIdx.x, z = blockIdx.z;
    if (z == 0) {
        for (int i = blockIdx.x * 256 + t; i < Hn * Hn; i += 512 * 256) {
            int h = i & (Hn - 1), j = i >> 9;
            float w0 = lnw[j];
            g_AuT[i] = Wu[(size_t)h * C3n + j] * w0;
            g_AvT[i] = Wv[(size_t)h * C3n + j] * w0;
        }
        for (int i = blockIdx.x * 256 + t; i < Hn * Hn; i += 512 * 256) {
            int j = i & (Hn - 1), h = i >> 9;
            float w1 = lnw[Hn + j];
            g_Bu[i] = Wu[(size_t)h * C3n + Hn + j] * w1;
            g_Bv[i] = Wv[(size_t)h * C3n + Hn + j] * w1;
        }
    } else if (z == 1) {
        // fp16 A-fragment pack (m16n8k16):
        // w = ((((ht*16+jc)*8+mtl)*2+kt)*32+lane)*4 + r
        // h = ht*128+mtl*16+(lane>>2)+8*(r&1), j = jc*32+kt*16+(lane&3)*2+8*(r>>1) (+1 hi)
        for (int w = blockIdx.x * 256 + t; w < 131072; w += 512 * 256) {
            int r = w & 3, lane = (w >> 2) & 31, kt = (w >> 7) & 1, mtl = (w >> 8) & 7;
            int jc = (w >> 11) & 15, ht = (w >> 15) & 3;
            int h = ht * 128 + mtl * 16 + (lane >> 2) + 8 * (r & 1);
            int j = jc * 32 + kt * 16 + (lane & 3) * 2 + 8 * (r >> 1);
            float wl0 = lnw[2 * Hn + j], wl1 = lnw[2 * Hn + j + 1];
            float ul = Wu[(size_t)h * C3n + 2 * Hn + j] * wl0;
            float uh = Wu[(size_t)h * C3n + 2 * Hn + j + 1] * wl1;
            float vl = Wv[(size_t)h * C3n + 2 * Hn + j] * wl0;
            float vh = Wv[(size_t)h * C3n + 2 * Hn + j + 1] * wl1;
            g_CuF[w] = f16x2(uh, ul);
            g_CvF[w] = f16x2(vh, vl);
        }
    } else {
        int gw = blockIdx.x * 8 + (t >> 5);
        int lane = t & 31;
        if (gw >= Hn) return;
        float gu = 0.f, cu = 0.f, gv = 0.f, cv = 0.f;
        for (int c = lane; c < C3n; c += 32) {
            float wl = lnw[c], bl = lnb[c];
            float a = Wu[(size_t)gw * C3n + c], d = Wv[(size_t)gw * C3n + c];
            gu += a * wl; cu += a * bl; gv += d * wl; cv += d * bl;
        }
        #pragma unroll
        for (int o = 16; o; o >>= 1) {
            gu += __shfl_xor_sync(0xffffffffu, gu, o);
            cu += __shfl_xor_sync(0xffffffffu, cu, o);
            gv += __shfl_xor_sync(0xffffffffu, gv, o);
            cv += __shfl_xor_sync(0xffffffffu, cv, o);
        }
        if (lane == 0) {
            g_gu[gw] = gu; g_cu[gw] = cu + bu[gw];
            g_gv[gw] = gv; g_cv[gw] = cv + bv[gw];
        }
    }
}

// ---------------- fp32 GEMM body; NT: C[m][n] = sum_k A[m][k]*B[n][k] ----------------
template<bool NT>
__device__ __forceinline__ void gemm_body(const float* __restrict__ A,
                                          const float* __restrict__ Bm,
                                          float* __restrict__ C,
                                          int N, int Kd, int ldc) {
    __shared__ __align__(16) float As[16][68];
    __shared__ __align__(16) float Bs[16][68];
    const int t  = threadIdx.x;
    const int tx = t & 15, ty = t >> 4;
    const int bm = blockIdx.y * 64, bn = blockIdx.x * 64;
    float acc[4][4] = {};
    for (int kb = 0; kb < Kd; kb += 16) {
        #pragma unroll
        for (int l = 0; l < 4; l++) {
            int e = t + l * 256;
            int m = e >> 4, kk = e & 15;
            As[kk][m] = A[(size_t)(bm + m) * Kd + kb + kk];
            if (NT) {
                Bs[kk][m] = Bm[(size_t)(bn + m) * Kd + kb + kk];
            } else {
                int n = e & 63, k2 = e >> 6;
                Bs[k2][n] = Bm[(size_t)(kb + k2) * N + bn + n];
            }
        }
        __syncthreads();
        #pragma unroll
        for (int kk = 0; kk < 16; kk++) {
            float4 a = *(const float4*)&As[kk][ty * 4];
            float4 b = *(const float4*)&Bs[kk][tx * 4];
            float aw[4] = {a.x, a.y, a.z, a.w};
            float bw[4] = {b.x, b.y, b.z, b.w};
            #pragma unroll
            for (int i = 0; i < 4; i++)
                #pragma unroll
                for (int j = 0; j < 4; j++)
                    acc[i][j] += aw[i] * bw[j];
        }
        __syncthreads();
    }
    #pragma unroll
    for (int i = 0; i < 4; i++) {
        float4 o = make_float4(acc[i][0], acc[i][1], acc[i][2], acc[i][3]);
        *(float4*)&C[(size_t)(bm + ty * 4 + i) * ldc + bn + tx * 4] = o;
    }
}

// NT projections directly on raw weights: qproj[m][h] = sum_d Q[m][d]*Wq[h][d]
__global__ __launch_bounds__(256) void gemm_proj(const float* __restrict__ Q,
                                                 const float* __restrict__ K,
                                                 const float* __restrict__ Wq,
                                                 const float* __restrict__ Wk) {
    if (blockIdx.z == 0) gemm_body<true>(Q, Wq, g_qproj, Hn, QDn, Hn);
    else                 gemm_body<true>(K, Wk, g_kproj, Hn, QDn, Hn);
}

// hidden-term GEMMs + LN stats + fp16 K convert in one launch. grid (8, 64, 8).
__global__ __launch_bounds__(256) void gemm_hs() {
    const int z = blockIdx.z;
    const int t = threadIdx.x;
    if (z < 6) {
        if (blockIdx.y >= 8) return;
        switch (z) {
            case 0: gemm_body<false>(g_qproj, g_AuT, g_ruq, Hn, Hn, Hn); return;
            case 1: gemm_body<false>(g_qproj, g_AvT, g_rvq, Hn, Hn, Hn); return;
            default: break;
        }
        if (blockIdx.x >= 4) return;
        const int b = (z - 2) >> 1;
        const float* kp = g_kproj + (size_t)b * KLn * Hn;
        if ((z & 1) == 0) gemm_body<true>(g_Bu, kp, g_rukT + (size_t)b * Hn * KLn, KLn, Hn, KLn);
        else              gemm_body<true>(g_Bv, kp, g_rvkT + (size_t)b * Hn * KLn, KLn, Hn, KLn);
        return;
    }
    if (z == 7) {
        // fp16x2 convert of kproj
        int i = (blockIdx.y * 8 + blockIdx.x) * 256 + t;   // 0..131071
        g_kprojH[i] = f16x2(g_kproj[2 * i + 1], g_kproj[2 * i]);
        return;
    }
    // z == 6: LN stats; block handles one bq, all 256 k
    __shared__ __align__(16) float qrow[Hn];
    __shared__ float s1s[KLn], s2s[KLn], sqv[2];
    const int warp = t >> 5, lane = t & 31;
    const int bq = blockIdx.y * 8 + blockIdx.x;
    const int b = bq >> 8;
    const float* qp = g_qproj + (size_t)bq * Hn;
    qrow[t] = qp[t]; qrow[t + 256] = qp[t + 256];
    __syncthreads();
    if (warp == 0) {
        float s1 = 0.f, s2 = 0.f;
        #pragma unroll
        for (int j = lane; j < Hn; j += 32) { float v = qrow[j]; s1 += v; s2 += v * v; }
        #pragma unroll
        for (int o = 16; o; o >>= 1) {
            s1 += __shfl_xor_sync(0xffffffffu, s1, o);
            s2 += __shfl_xor_sync(0xffffffffu, s2, o);
        }
        if (lane == 0) { sqv[0] = s1; sqv[1] = s2; }
    }
    const float* kpbase = g_kproj + (size_t)b * KLn * Hn;
    for (int r = 0; r < 32; r++) {
        int kk = warp * 32 + r;
        const float* kp = kpbase + (size_t)kk * Hn;
        float sk = 0.f, sk2 = 0.f, d1 = 0.f, d2 = 0.f;
        for (int j = lane; j < Hn; j += 32) {
            float kv = kp[j];
            float p  = kv * qrow[j];
            sk += kv; sk2 += kv * kv; d1 += p; d2 += p * p;
        }
        #pragma unroll
        for (int o = 16; o; o >>= 1) {
            sk  += __shfl_xor_sync(0xffffffffu, sk,  o);
            sk2 += __shfl_xor_sync(0xffffffffu, sk2, o);
            d1  += __shfl_xor_sync(0xffffffffu, d1,  o);
            d2  += __shfl_xor_sync(0xffffffffu, d2,  o);
        }
        if (lane == 0) { s1s[kk] = sk + d1; s2s[kk] = sk2 + d2; }
    }
    __syncthreads();
    {
        float mu = (sqv[0] + s1s[t]) * (1.f / C3n);
        float e2 = (sqv[1] + s2s[t]) * (1.f / C3n);
        g_mu[(size_t)bq * KLn + t] = mu;
        g_rs[(size_t)bq * KLn + t] = rsqrtf(e2 - mu * mu + EPSf);
    }
}

// ---------------- main mma.sync kernel (fp16 m16n8k16, 2 CTAs/SM) ----------------
// grid (4, 512) = (k-quarter, bq). 256 threads / 8 warps: hg=warp&3 (32h), kg=warp>>2 (32k).
// 32-j chunks, DEPTH-4 pipeline, R13 ordering with d=2 lead:
//   iter i: stage(i+2) [issued pre-wait: overlaps slack; writes chunk i-2's
//           buffer, reads done before barrier(i-1)]; wait_group(2) [stage(i)
//           done]; barrier; consume chunk i.  One barrier/iter, race-free.
#define STAGE_SZ 20480   // CuF 8192 | CvF 8192 | KR 4096 (64 rows)
#define OFF_STG  0       // 4 stages = 81920
#define OFF_QH   81920   // 1024 (fp16x2 q pairs)
#define OFF_HV   82944   // 4 ht x 7 arrays x 128 floats = 14336
#define OFF_MU   97280   // 256 (holds mu*rs, 64 k)
#define OFF_RS   97536   // 256
#define OFF_SP   97792   // 1024
#define SM_SZ    98816

__global__ __launch_bounds__(256, 2) void gated_mma(const float* __restrict__ Wo,
                                                    const float* __restrict__ bo,
                                                    float* __restrict__ out) {
    extern __shared__ __align__(16) char sm[];
    const u32 sb = smem_u32(sm);
    const int t = threadIdx.x, lane = t & 31, warp = t >> 5;
    const int hg = warp & 3, kg = warp >> 2;        // kg in {0,1}
    const int q = lane >> 2, tid = lane & 3;
    const int kq = blockIdx.x, bq = blockIdx.y, b = bq >> 8;

    // fp16x2 q pairs
    u32* qh = (u32*)(sm + OFF_QH);
    {
        const float* qp = g_qproj + (size_t)bq * Hn + 2 * t;
        qh[t] = f16x2(qp[1], qp[0]);
    }
    float* muS = (float*)(sm + OFF_MU);
    float* rsS = (float*)(sm + OFF_RS);
    if (t < 64) {
        float rs = g_rs[(size_t)bq * KLn + kq * 64 + t];
        rsS[t] = rs;
        muS[t] = g_mu[(size_t)bq * KLn + kq * 64 + t] * rs;   // mu*rs
    }
    // preload epilogue constants for all 4 ht chunks
    float* hvA = (float*)(sm + OFF_HV);
    #pragma unroll
    for (int i = t; i < Hn; i += 256) {
        const int ht = i >> 7, hl = i & 127;
        float* hb = hvA + ht * 896;
        hb[hl]       = g_ruq[(size_t)bq * Hn + i];
        hb[128 + hl] = g_rvq[(size_t)bq * Hn + i];
        hb[256 + hl] = g_gu[i];
        hb[384 + hl] = g_cu[i];
        hb[512 + hl] = g_gv[i];
        hb[640 + hl] = g_cv[i];
        hb[768 + hl] = Wo[i];
    }

    float accU[2][4][4] = {}, accV[2][4][4] = {};
    float part[4][2] = {};

    const char* kpB = (const char*)(g_kprojH + ((size_t)(b * KLn) + kq * 64) * 256);

    auto stage = [&](int s) {
        const int jc = s & 15;
        const u32 base = sb + OFF_STG + (u32)(s & 3) * STAGE_SZ;
        const char* su = (const char*)(g_CuF + s * 2048);
        const char* sv = (const char*)(g_CvF + s * 2048);
        cpasync16(base + t * 16,               su + t * 16);
        cpasync16(base + (t + 256) * 16,       su + (t + 256) * 16);
        cpasync16(base + 8192 + t * 16,        sv + t * 16);
        cpasync16(base + 8192 + (t + 256) * 16, sv + (t + 256) * 16);
        // KR: 256 chunks of 16B (64 rows), chunk-swizzled
        {
            int k = t >> 2, c = t & 3;
            u32 dst = base + 16384 + (u32)((k >> 3) * 512 + c * 128 + (k & 7) * 16);
            cpasync16(dst, kpB + (size_t)k * 1024 + jc * 64 + c * 16);
        }
        cp_commit();
    };

    stage(0); stage(1);

    // per-lane constant base into swizzled KR (block = kg*4 + nt, row q', word tid)
    const u32 krOff = (u32)(kg * 4 * 512 + q * 16 + tid * 4);

    for (int it = 0; it < 64; it++) {
        if (it < 62) { stage(it + 2); asm volatile("cp.async.wait_group 2;" ::: "memory"); }
        else if (it == 62) asm volatile("cp.async.wait_group 1;" ::: "memory");
        else               asm volatile("cp.async.wait_group 0;" ::: "memory");
        __syncthreads();

        const u32 base = sb + OFF_STG + (u32)(it & 3) * STAGE_SZ;
        const u32 aU = base, aV = base + 8192;
        const u32 krb = base + 16384 + krOff;
        const u32 qhb = sb + OFF_QH + (u32)(((it & 15) * 16 + tid) * 4);

        #pragma unroll
        for (int kt = 0; kt < 2; kt++) {
            const u32 qh0 = lds32(qhb + (u32)(kt * 32));
            const u32 qh1 = lds32(qhb + (u32)(kt * 32 + 16));
            u32 bfr[4][2];
            #pragma unroll
            for (int nt = 0; nt < 4; nt++) {
                const u32 a0 = krb + (u32)(nt * 512 + kt * 256);
                u32 k0 = lds32(a0);
                u32 k1 = lds32(a0 + 128);
                bfr[nt][0] = hmul2(k0, qh0);
                bfr[nt][1] = hmul2(k1, qh1);
            }
            u32 au[2][4], av[2][4];
            #pragma unroll
            for (int mt = 0; mt < 2; mt++) {
                const u32 fo = (u32)((((hg * 2 + mt) * 2 + kt) * 32 + lane) * 16);
                lds128(aU + fo, au[mt]);
                lds128(aV + fo, av[mt]);
            }
            #pragma unroll
            for (int mt = 0; mt < 2; mt++)
                #pragma unroll
                for (int nt = 0; nt < 4; nt++) {
                    mma16(accU[mt][nt], au[mt], bfr[nt]);
                    mma16(accV[mt][nt], av[mt], bfr[nt]);
                }
        }

        if ((it & 15) == 15) {
            const int ht = it >> 4;
            const float* hv = hvA + ht * 896;
            const float* ruT = g_rukT + ((size_t)b * Hn + ht * 128) * KLn + kq * 64;
            const float* rvT = g_rvkT + ((size_t)b * Hn + ht * 128) * KLn + kq * 64;
            #pragma unroll
            for (int mt = 0; mt < 2; mt++) {
                #pragma unroll
                for (int rr = 0; rr < 2; rr++) {
                    const int hl = (hg * 2 + mt) * 16 + q + rr * 8;
                    const float ruq = hv[hl],       rvq = hv[128 + hl];
                    const float gu  = hv[256 + hl], cu  = hv[384 + hl];
                    const float gv  = hv[512 + hl], cv  = hv[640 + hl];
                    const float wo  = hv[768 + hl];
                    const float* ruB = ruT + (size_t)hl * KLn + kg * 32 + tid * 2;
                    const float* rvB = rvT + (size_t)hl * KLn + kg * 32 + tid * 2;
                    #pragma unroll
                    for (int nt = 0; nt < 4; nt++) {
                        float2 ru2 = *(const float2*)(ruB + nt * 8);
                        float2 rv2 = *(const float2*)(rvB + nt * 8);
                        #pragma unroll
                        for (int e = 0; e < 2; e++) {
                            const int kc = kg * 32 + nt * 8 + tid * 2 + e;
                            const float mrs = muS[kc], rs = rsS[kc];
                            const float du = accU[mt][nt][rr * 2 + e];
                            const float dv = accV[mt][nt][rr * 2 + e];
                            const float ruk = e ? ru2.y : ru2.x;
                            const float rvk = e ? rv2.y : rv2.x;
                            float U = rs * (du + ruq + ruk) - mrs * gu + cu;
                            float V = rs * (dv + rvq + rvk) - mrs * gv + cv;
                            float G = 0.5f * V * (1.0f + erff(V * 0.70710678118654752440f));
                            part[nt][e] += wo * (U * G);
                            accU[mt][nt][rr * 2 + e] = 0.f;
                            accV[mt][nt][rr * 2 + e] = 0.f;
                        }
                    }
                }
            }
        }
    }

    // reduce across q-lanes (same tid), then across the 4 hg warps via smem
    #pragma unroll
    for (int nt = 0; nt < 4; nt++)
        #pragma unroll
        for (int e = 0; e < 2; e++) {
            float v = part[nt][e];
            v += __shfl_xor_sync(0xffffffffu, v, 4);
            v += __shfl_xor_sync(0xffffffffu, v, 8);
            v += __shfl_xor_sync(0xffffffffu, v, 16);
            part[nt][e] = v;
        }
    float* sp = (float*)(sm + OFF_SP);
    __syncthreads();
    if (q == 0) {
        #pragma unroll
        for (int nt = 0; nt < 4; nt++)
            #pragma unroll
            for (int e = 0; e < 2; e++)
                sp[hg * 64 + kg * 32 + nt * 8 + tid * 2 + e] = part[nt][e];
    }
    __syncthreads();
    if (t < 64) {
        float r = sp[t] + sp[64 + t] + sp[128 + t] + sp[192 + t] + bo[0];
        out[(size_t)bq * KLn + kq * 64 + t] = r;
    }
}

// ---------------- launch ----------------
extern "C" void kernel_launch(void* const* d_in, const int* in_sizes, int n_in,
                              void* d_out, int out_size) {
    const float* Q   = (const float*)d_in[0];
    const float* K   = (const float*)d_in[1];
    const float* Wq  = (const float*)d_in[2];
    const float* Wk  = (const float*)d_in[3];
    const float* lnw = (const float*)d_in[4];
    const float* lnb = (const float*)d_in[5];
    const float* Wu  = (const float*)d_in[6];
    const float* bu  = (const float*)d_in[7];
    const float* Wv  = (const float*)d_in[8];
    const float* bv  = (const float*)d_in[9];
    const float* Wo  = (const float*)d_in[10];
    const float* bo  = (const float*)d_in[11];
    float* out = (float*)d_out;

    static int smem_set = 0;
    if (!smem_set) {
        cudaFuncSetAttribute(gated_mma, cudaFuncAttributeMaxDynamicSharedMemorySize, SM_SZ);
        smem_set = 1;
    }

    prep_w<<<dim3(512, 1, 3), 256>>>(Wu, Wv, lnw, lnb, bu, bv);
    gemm_proj<<<dim3(8, 8, 2), 256>>>(Q, K, Wq, Wk);
    gemm_hs<<<dim3(8, 64, 8), 256>>>();
    gated_mma<<<dim3(4, 512), 256, SM_SZ>>>(Wo, bo, out);
}